// round 1
// baseline (speedup 1.0000x reference)
#include <cuda_runtime.h>

#define NT 1024
#define NHEAD 16
#define DH 64
#define NN (1024u*1024u)

// scratch (device globals: allocation-free)
__device__ float g_bias[16u*1024u*1024u]; // [h][i][j]
__device__ float g_qt[1024*1024];         // [dim_inner][token], pre-scaled by 0.125
__device__ float g_kt[1024*1024];         // [dim_inner][token]
__device__ float g_v [1024*1024];         // [token][dim_inner]
__device__ float g_g [1024*1024];         // sigmoid gates, [token][dim_inner]
__device__ float g_o [1024*1024];         // gated attention out, [token][dim_inner]

// ---------------------------------------------------------------------------
// Bias kernel: LayerNorm over 128 pair features + project to 16 heads.
// One warp per (i,j). Block = 256 thr handles i=blockIdx.y, 128 j's.
// ---------------------------------------------------------------------------
__global__ __launch_bounds__(256, 2) void bias_kernel(
    const float* __restrict__ pw, const float* __restrict__ gamma,
    const float* __restrict__ beta, const float* __restrict__ Wb)
{
    __shared__ float tile[16][129];
    int tid  = threadIdx.x;
    int lane = tid & 31, warp = tid >> 5;
    int i  = blockIdx.y;
    int j0 = blockIdx.x * 128;
    int p0 = lane * 4;

    // per-lane weight slice in registers: wg[q][h] = gamma[p0+q]*W[p0+q][h]
    float wg[4][16];
    float binit[16];
    {
        float4 gg = *(const float4*)(gamma + p0);
        float4 bb = *(const float4*)(beta  + p0);
        float g4[4] = {gg.x, gg.y, gg.z, gg.w};
        float b4[4] = {bb.x, bb.y, bb.z, bb.w};
#pragma unroll
        for (int h = 0; h < 16; h++) binit[h] = 0.f;
#pragma unroll
        for (int q = 0; q < 4; q++) {
#pragma unroll
            for (int h = 0; h < 16; h++) {
                float w = Wb[(p0 + q) * 16 + h];
                wg[q][h]  = g4[q] * w;
                binit[h] += b4[q] * w;
            }
        }
    }

    const float4* base = (const float4*)pw + ((size_t)i * 1024 + j0) * 32;
    float4 x = base[(size_t)warp * 32 + lane];   // prefetch first
#pragma unroll 1
    for (int t = 0; t < 16; t++) {
        int jj = warp + 8 * t;
        float4 xn;
        if (t < 15) xn = base[(size_t)(jj + 8) * 32 + lane];

        float s  = x.x + x.y + x.z + x.w;
        float ss = x.x*x.x + x.y*x.y + x.z*x.z + x.w*x.w;
#pragma unroll
        for (int off = 16; off >= 1; off >>= 1) {
            s  += __shfl_xor_sync(0xffffffffu, s,  off);
            ss += __shfl_xor_sync(0xffffffffu, ss, off);
        }
        float mu  = s * 0.0078125f;
        float var = ss * 0.0078125f - mu * mu;
        float rs  = rsqrtf(var + 1e-5f);
        float t0 = (x.x - mu) * rs, t1 = (x.y - mu) * rs;
        float t2 = (x.z - mu) * rs, t3 = (x.w - mu) * rs;

        float acc[16];
#pragma unroll
        for (int h = 0; h < 16; h++)
            acc[h] = binit[h] + t0*wg[0][h] + t1*wg[1][h] + t2*wg[2][h] + t3*wg[3][h];

        // 16-value butterfly reduce across warp (16 shfl, not 80):
#pragma unroll
        for (int q = 0; q < 8; q++) {
            bool hi = (lane & 16);
            float keep = hi ? acc[q + 8] : acc[q];
            float send = hi ? acc[q]     : acc[q + 8];
            acc[q] = keep + __shfl_xor_sync(0xffffffffu, send, 16);
        }
#pragma unroll
        for (int q = 0; q < 4; q++) {
            bool hi = (lane & 8);
            float keep = hi ? acc[q + 4] : acc[q];
            float send = hi ? acc[q]     : acc[q + 4];
            acc[q] = keep + __shfl_xor_sync(0xffffffffu, send, 8);
        }
#pragma unroll
        for (int q = 0; q < 2; q++) {
            bool hi = (lane & 4);
            float keep = hi ? acc[q + 2] : acc[q];
            float send = hi ? acc[q]     : acc[q + 2];
            acc[q] = keep + __shfl_xor_sync(0xffffffffu, send, 4);
        }
        {
            bool hi = (lane & 2);
            float keep = hi ? acc[1] : acc[0];
            float send = hi ? acc[0] : acc[1];
            acc[0] = keep + __shfl_xor_sync(0xffffffffu, send, 2);
        }
        acc[0] += __shfl_xor_sync(0xffffffffu, acc[0], 1);
        int h = (lane >> 1) & 15;
        if ((lane & 1) == 0) tile[h][jj] = acc[0];
        x = xn;
    }
    __syncthreads();
    size_t obase = (size_t)i * 1024 + j0;
    for (int e = tid; e < 2048; e += 256) {
        int h = e >> 7, jj = e & 127;
        g_bias[(size_t)h * NN + obase + jj] = tile[h][jj];
    }
}

// ---------------------------------------------------------------------------
// 1024x1024x1024 fp32 GEMM, C = A @ B, 64x64 block tile, BK=16, 4x4 per thread.
// mode: 0=natural  1=*0.125 + transposed  2=transposed  3=sigmoid(x+aux[n])
// asel: 0=Aext 5=g_o;  csel: 0=Cext 1=g_qt 2=g_kt 3=g_v 4=g_g
// ---------------------------------------------------------------------------
__global__ __launch_bounds__(256, 2) void gemm1024(
    const float* __restrict__ Aext, int asel,
    const float* __restrict__ B,
    float* __restrict__ Cext, int csel,
    const float* __restrict__ aux, int mode)
{
    const float* A = (asel == 5) ? (const float*)g_o : Aext;
    float* C = Cext;
    if      (csel == 1) C = g_qt;
    else if (csel == 2) C = g_kt;
    else if (csel == 3) C = g_v;
    else if (csel == 4) C = g_g;

    __shared__ float As[16][68];
    __shared__ float Bs[16][68];
    int tid  = threadIdx.x;
    int row0 = blockIdx.y * 64, col0 = blockIdx.x * 64;
    int tr4 = (tid >> 4) * 4;     // row micro-tile
    int tc4 = (tid & 15) * 4;     // col micro-tile
    int la_r = tid >> 2;
    int la_c = (tid & 3) * 4;
    int lb_k = tid >> 4;
    int lb_c = (tid & 15) * 4;
    const float* Aptr = A + (size_t)(row0 + la_r) * 1024 + la_c;
    const float* Bptr = B + (size_t)lb_k * 1024 + col0 + lb_c;

    float acc[4][4] = {};
    float4 av = *(const float4*)(Aptr);
    float4 bv = *(const float4*)(Bptr);
#pragma unroll 1
    for (int k0 = 0; k0 < 1024; k0 += 16) {
        As[la_c + 0][la_r] = av.x;
        As[la_c + 1][la_r] = av.y;
        As[la_c + 2][la_r] = av.z;
        As[la_c + 3][la_r] = av.w;
        *(float4*)&Bs[lb_k][lb_c] = bv;
        __syncthreads();
        if (k0 + 16 < 1024) {   // prefetch next tiles during compute
            av = *(const float4*)(Aptr + k0 + 16);
            bv = *(const float4*)(Bptr + (size_t)(k0 + 16) * 1024);
        }
#pragma unroll
        for (int kk = 0; kk < 16; kk++) {
            float4 a = *(const float4*)&As[kk][tr4];
            float4 b = *(const float4*)&Bs[kk][tc4];
            float ar[4] = {a.x, a.y, a.z, a.w};
            float br[4] = {b.x, b.y, b.z, b.w};
#pragma unroll
            for (int ii = 0; ii < 4; ii++)
#pragma unroll
                for (int jj = 0; jj < 4; jj++)
                    acc[ii][jj] += ar[ii] * br[jj];
        }
        __syncthreads();
    }

    if (mode == 0) {
#pragma unroll
        for (int ii = 0; ii < 4; ii++) {
            float4 v = make_float4(acc[ii][0], acc[ii][1], acc[ii][2], acc[ii][3]);
            *(float4*)(C + (size_t)(row0 + tr4 + ii) * 1024 + col0 + tc4) = v;
        }
    } else if (mode == 1) {
#pragma unroll
        for (int ii = 0; ii < 4; ii++)
#pragma unroll
            for (int jj = 0; jj < 4; jj++)
                C[(size_t)(col0 + tc4 + jj) * 1024 + row0 + tr4 + ii] = acc[ii][jj] * 0.125f;
    } else if (mode == 2) {
#pragma unroll
        for (int ii = 0; ii < 4; ii++)
#pragma unroll
            for (int jj = 0; jj < 4; jj++)
                C[(size_t)(col0 + tc4 + jj) * 1024 + row0 + tr4 + ii] = acc[ii][jj];
    } else {
#pragma unroll
        for (int ii = 0; ii < 4; ii++) {
            float vv[4];
#pragma unroll
            for (int jj = 0; jj < 4; jj++) {
                float z = acc[ii][jj] + aux[col0 + tc4 + jj];
                vv[jj] = 1.0f / (1.0f + __expf(-z));
            }
            float4 v = make_float4(vv[0], vv[1], vv[2], vv[3]);
            *(float4*)(C + (size_t)(row0 + tr4 + ii) * 1024 + col0 + tc4) = v;
        }
    }
}

// ---------------------------------------------------------------------------
// Flash attention with additive pair bias + fused gating.
// Block: 256 thr, 64 queries x head. Grid (16 qblocks, 16 heads).
// smem: Qt(d-major) + KV (Kt then V, dual-use) + P = exactly 48 KB.
// ---------------------------------------------------------------------------
__global__ __launch_bounds__(256) void attn_kernel()
{
    __shared__ float Qt[64][64];   // [d][q]
    __shared__ float KV[64][64];   // phase1: [d][k]   phase2: [k][d]
    __shared__ float Ps[64][64];   // [q][k]
    int tid = threadIdx.x;
    int h   = blockIdx.y;
    int q0  = blockIdx.x * 64;
    int tr4 = (tid >> 4) * 4;
    int tc4 = (tid & 15) * 4;

#pragma unroll
    for (int it = 0; it < 4; it++) {
        int e = tid + it * 256;
        int dd = e >> 4, rc = (e & 15) * 4;
        *(float4*)&Qt[dd][rc] =
            *(const float4*)(g_qt + (size_t)(h * 64 + dd) * 1024 + q0 + rc);
    }
    float m_i[4], l_i[4], o[4][4];
#pragma unroll
    for (int ii = 0; ii < 4; ii++) {
        m_i[ii] = -1e30f; l_i[ii] = 0.f;
#pragma unroll
        for (int jj = 0; jj < 4; jj++) o[ii][jj] = 0.f;
    }
    __syncthreads();

#pragma unroll 1
    for (int kb = 0; kb < 16; kb++) {
        int k0 = kb * 64;
        // K^T tile
#pragma unroll
        for (int it = 0; it < 4; it++) {
            int e = tid + it * 256;
            int dd = e >> 4, cc = (e & 15) * 4;
            *(float4*)&KV[dd][cc] =
                *(const float4*)(g_kt + (size_t)(h * 64 + dd) * 1024 + k0 + cc);
        }
        __syncthreads();

        // S = Q K^T (q pre-scaled) + bias
        float s[4][4];
#pragma unroll
        for (int ii = 0; ii < 4; ii++) {
            float4 bb = *(const float4*)(g_bias + (size_t)h * NN
                              + (size_t)(q0 + tr4 + ii) * 1024 + k0 + tc4);
            s[ii][0] = bb.x; s[ii][1] = bb.y; s[ii][2] = bb.z; s[ii][3] = bb.w;
        }
#pragma unroll 8
        for (int d = 0; d < 64; d++) {
            float4 qa = *(const float4*)&Qt[d][tr4];
            float4 ka = *(const float4*)&KV[d][tc4];
            float ar[4] = {qa.x, qa.y, qa.z, qa.w};
            float br[4] = {ka.x, ka.y, ka.z, ka.w};
#pragma unroll
            for (int ii = 0; ii < 4; ii++)
#pragma unroll
                for (int jj = 0; jj < 4; jj++)
                    s[ii][jj] += ar[ii] * br[jj];
        }

        // online softmax (reduce across the 16-lane tc group)
#pragma unroll
        for (int ii = 0; ii < 4; ii++) {
            float rm = fmaxf(fmaxf(s[ii][0], s[ii][1]), fmaxf(s[ii][2], s[ii][3]));
#pragma unroll
            for (int off = 8; off >= 1; off >>= 1)
                rm = fmaxf(rm, __shfl_xor_sync(0xffffffffu, rm, off));
            float mn   = fmaxf(m_i[ii], rm);
            float corr = __expf(m_i[ii] - mn);
            m_i[ii] = mn;
            float rsum = 0.f;
#pragma unroll
            for (int jj = 0; jj < 4; jj++) {
                s[ii][jj] = __expf(s[ii][jj] - mn);
                rsum += s[ii][jj];
            }
#pragma unroll
            for (int off = 8; off >= 1; off >>= 1)
                rsum += __shfl_xor_sync(0xffffffffu, rsum, off);
            l_i[ii] = l_i[ii] * corr + rsum;
#pragma unroll
            for (int jj = 0; jj < 4; jj++) o[ii][jj] *= corr;
        }
        __syncthreads();   // done reading Kt; Ps from prev iter consumed long ago

        // write P, load V into KV
#pragma unroll
        for (int ii = 0; ii < 4; ii++)
            *(float4*)&Ps[tr4 + ii][tc4] =
                make_float4(s[ii][0], s[ii][1], s[ii][2], s[ii][3]);
#pragma unroll
        for (int it = 0; it < 4; it++) {
            int e = tid + it * 256;
            int cc = e >> 4, dd = (e & 15) * 4;
            *(float4*)&KV[cc][dd] =
                *(const float4*)(g_v + (size_t)(k0 + cc) * 1024 + h * 64 + dd);
        }
        __syncthreads();

        // O += P @ V
#pragma unroll 8
        for (int c = 0; c < 64; c++) {
            float4 vv = *(const float4*)&KV[c][tc4];
            float vr[4] = {vv.x, vv.y, vv.z, vv.w};
            float pr[4];
#pragma unroll
            for (int ii = 0; ii < 4; ii++) pr[ii] = Ps[tr4 + ii][c];
#pragma unroll
            for (int ii = 0; ii < 4; ii++)
#pragma unroll
                for (int jj = 0; jj < 4; jj++)
                    o[ii][jj] += pr[ii] * vr[jj];
        }
        __syncthreads();
    }

    // normalize, gate, store
#pragma unroll
    for (int ii = 0; ii < 4; ii++) {
        float inv = 1.0f / l_i[ii];
        size_t off = (size_t)(q0 + tr4 + ii) * 1024 + h * 64 + tc4;
        float4 gg = *(const float4*)(g_g + off);
        float4 ov;
        ov.x = o[ii][0] * inv * gg.x;
        ov.y = o[ii][1] * inv * gg.y;
        ov.z = o[ii][2] * inv * gg.z;
        ov.w = o[ii][3] * inv * gg.w;
        *(float4*)(g_o + off) = ov;
    }
}

// ---------------------------------------------------------------------------
extern "C" void kernel_launch(void* const* d_in, const int* in_sizes, int n_in,
                              void* d_out, int out_size)
{
    const float* single = (const float*)d_in[0];
    const float* pw     = (const float*)d_in[1];
    const float* gamma  = (const float*)d_in[2];
    const float* beta   = (const float*)d_in[3];
    const float* Wb     = (const float*)d_in[4];
    const float* Wq     = (const float*)d_in[5];
    const float* Wk     = (const float*)d_in[6];
    const float* Wv     = (const float*)d_in[7];
    const float* Wg     = (const float*)d_in[8];
    const float* bg     = (const float*)d_in[9];
    const float* Wo     = (const float*)d_in[10];
    float* out = (float*)d_out;

    dim3 bgrid(8, 1024);
    bias_kernel<<<bgrid, 256>>>(pw, gamma, beta, Wb);

    dim3 ggrid(16, 16);
    gemm1024<<<ggrid, 256>>>(single, 0, Wq, nullptr, 1, nullptr, 1); // q: *0.125, T
    gemm1024<<<ggrid, 256>>>(single, 0, Wk, nullptr, 2, nullptr, 2); // k: T
    gemm1024<<<ggrid, 256>>>(single, 0, Wv, nullptr, 3, nullptr, 0); // v
    gemm1024<<<ggrid, 256>>>(single, 0, Wg, nullptr, 4, bg,      3); // gates

    dim3 agrid(16, 16);
    attn_kernel<<<agrid, 256>>>();

    gemm1024<<<ggrid, 256>>>(nullptr, 5, Wo, out, 0, nullptr, 0);    // final proj
}